// round 17
// baseline (speedup 1.0000x reference)
#include <cuda_runtime.h>
#include <cstdint>

// ---------------- problem constants ----------------
#define BATCH 2
#define SEQ   1024
#define DMODEL 768
#define FFDIM 3072
#define NHEAD 12
#define HDIM  64
#define NLAYER 4
#define VOCAB 50257
#define VPAD  50304          // 393*128, divisible by 128
#define ROWS (BATCH*SEQ)     // 2048

// ---------------- scratch ----------------
__device__ __align__(128) float g_x  [ROWS*DMODEL];
__device__ __align__(128) float g_h  [ROWS*DMODEL];
__device__ __align__(128) float g_qkv[ROWS*3*DMODEL];
__device__ __align__(128) float g_o  [ROWS*DMODEL];
__device__ __align__(128) float g_ff [ROWS*FFDIM];
__device__ __align__(128) float g_wlm[(size_t)DMODEL*VPAD];   // padded lm_head weights

__device__ __forceinline__ float gelu_tanh(float x) {
    const float c = 0.7978845608028654f;
    float x3 = x * x * x;
    return 0.5f * x * (1.0f + tanhf(c * (x + 0.044715f * x3)));
}
__device__ __forceinline__ uint32_t smem_u32(const void* p) {
    uint32_t a;
    asm("{ .reg .u64 t; cvta.to.shared.u64 t, %1; cvt.u32.u64 %0, t; }" : "=r"(a) : "l"(p));
    return a;
}

// packed f32x2 ops (element-wise rn -- numerics identical to scalar fmaf)
#define FMA2(d, a, b) \
    asm("fma.rn.f32x2 %0, %1, %2, %0;" : "+l"(d) : "l"(a), "l"(b))
#define MUL2(d, a) \
    asm("mul.rn.f32x2 %0, %0, %1;" : "+l"(d) : "l"(a))
#define PACK_DUP(d, f) \
    asm("mov.b64 %0, {%1,%1};" : "=l"(d) : "r"(__float_as_uint(f)))
#define UNPK(lo, hi, p) \
    asm("mov.b64 {%0,%1}, %2;" : "=r"(lo), "=r"(hi) : "l"(p))

// cp.async
#define CP_A16(saddr, gptr) \
    asm volatile("cp.async.cg.shared.global [%0], [%1], 16;" :: "r"(saddr), "l"(gptr))
#define CP_A4(saddr, gptr) \
    asm volatile("cp.async.ca.shared.global [%0], [%1], 4;" :: "r"(saddr), "l"(gptr))
#define CP_COMMIT() asm volatile("cp.async.commit_group;" ::: "memory")
#define CP_WAIT1()  asm volatile("cp.async.wait_group 1;" ::: "memory")
#define CP_WAIT0()  asm volatile("cp.async.wait_group 0;" ::: "memory")

// ---------------- fp32 SGEMM: FFMA2 core + 3-stage cp.async, 1 barrier/chunk ----------------
// C[M,*] = A[M,K] @ B[K,*] ; B row stride = Bstride (128-divisible, padded)
// EPI: 0 = +bias, 1 = +bias+gelu, 2 = +bias+resid, 3 = plain, store-guard col<Cstride
template<int EPI>
__global__ void __launch_bounds__(256, 2)
sgemm(const float* __restrict__ A, const float* __restrict__ B,
      const float* __restrict__ bias, const float* __restrict__ resid,
      float* __restrict__ C, int K, int Bstride, int Cstride)
{
    __shared__ float As[3][8][128];
    __shared__ float Bs[3][8][128];

    const int tid = threadIdx.x;
    const int tx = tid & 15, ty = tid >> 4;
    const int blockM = blockIdx.y * 128;
    const int blockN = blockIdx.x * 128;

    const int aRow = tid >> 1;            // 0..127
    const int aCol = (tid & 1) * 4;       // 0 or 4
    const int bRow = tid >> 5;            // 0..7
    const int bCol = (tid & 31) * 4;      // 0..124

    const float* Aptr = A + (size_t)(blockM + aRow) * K + aCol;
    const float* Bptr = B + (size_t)bRow * Bstride + blockN + bCol;

    const uint32_t sAs = smem_u32(&As[0][0][0]);
    const uint32_t sBs = smem_u32(&Bs[0][0][0]);
    // per-thread fixed smem targets (stage-relative)
    const uint32_t aDst = sAs + ((uint32_t)aCol * 128 + aRow) * 4;   // + s*4096 + i*512
    const uint32_t bDst = sBs + ((uint32_t)bRow * 128 + bCol) * 4;   // + s*4096

    const int NB = K >> 3;

    auto issue = [&](int bk) {
        const uint32_t so = (uint32_t)(bk % 3) * 4096;
        const float* ag = Aptr + bk * 8;
        CP_A4(aDst + so +    0, ag + 0);
        CP_A4(aDst + so +  512, ag + 1);
        CP_A4(aDst + so + 1024, ag + 2);
        CP_A4(aDst + so + 1536, ag + 3);
        CP_A16(bDst + so, Bptr + (size_t)bk * 8 * Bstride);
        CP_COMMIT();
    };

    // acc2[i][p]: row i (8 rows), column pair p (4 pairs = 8 cols)
    unsigned long long acc2[8][4];
#pragma unroll
    for (int i = 0; i < 8; i++)
#pragma unroll
        for (int p = 0; p < 4; p++) acc2[i][p] = 0ull;

    issue(0);
    issue(1);

    for (int bk = 0; bk < NB; bk++) {
        if (bk + 1 < NB) CP_WAIT1(); else CP_WAIT0();
        __syncthreads();
        if (bk + 2 < NB) issue(bk + 2);

        const int s = bk % 3;
#pragma unroll
        for (int k = 0; k < 8; k++) {
            float ar[8];
            *(float4*)&ar[0] = *(const float4*)&As[s][k][ty * 4];
            *(float4*)&ar[4] = *(const float4*)&As[s][k][ty * 4 + 64];
            unsigned long long b2[4];
            {
                ulonglong2 q0 = *(const ulonglong2*)&Bs[s][k][tx * 4];
                ulonglong2 q1 = *(const ulonglong2*)&Bs[s][k][tx * 4 + 64];
                b2[0] = q0.x; b2[1] = q0.y; b2[2] = q1.x; b2[3] = q1.y;
            }
#pragma unroll
            for (int i = 0; i < 8; i++) {
                unsigned long long a2;
                PACK_DUP(a2, ar[i]);
                FMA2(acc2[i][0], a2, b2[0]);
                FMA2(acc2[i][1], a2, b2[1]);
                FMA2(acc2[i][2], a2, b2[2]);
                FMA2(acc2[i][3], a2, b2[3]);
            }
        }
    }

    // unpack accumulators
    float accf[8][8];
#pragma unroll
    for (int i = 0; i < 8; i++)
#pragma unroll
        for (int p = 0; p < 4; p++) {
            uint32_t lo, hi;
            UNPK(lo, hi, acc2[i][p]);
            accf[i][2 * p]     = __uint_as_float(lo);
            accf[i][2 * p + 1] = __uint_as_float(hi);
        }

    // ---------------- epilogue ----------------
    float bf[2][4];
    if (EPI != 3) {
#pragma unroll
        for (int jh = 0; jh < 2; jh++)
            *(float4*)&bf[jh][0] = *(const float4*)(bias + blockN + tx * 4 + jh * 64);
    }
#pragma unroll
    for (int i = 0; i < 8; i++) {
        int row = blockM + ty * 4 + (i & 3) + (i >> 2) * 64;
#pragma unroll
        for (int jh = 0; jh < 2; jh++) {
            int col = blockN + tx * 4 + jh * 64;
            float v[4];
#pragma unroll
            for (int j = 0; j < 4; j++) {
                v[j] = accf[i][jh * 4 + j];
                if (EPI != 3) v[j] += bf[jh][j];
                if (EPI == 1) v[j] = gelu_tanh(v[j]);
            }
            if (EPI == 2) {
                float4 rv = *(const float4*)(resid + (size_t)row * Cstride + col);
                v[0] += rv.x; v[1] += rv.y; v[2] += rv.z; v[3] += rv.w;
            }
            if (EPI == 3) {
#pragma unroll
                for (int j = 0; j < 4; j++)
                    if (col + j < Cstride) C[(size_t)row * Cstride + col + j] = v[j];
            } else {
                *(float4*)(C + (size_t)row * Cstride + col) = make_float4(v[0], v[1], v[2], v[3]);
            }
        }
    }
}

// ---------------- flash-style attention, FFMA2 inner products ----------------
#define AQ 64
#define AK 64
#define APITCH 68
#define QS_OFF 0
#define KS_OFF (64*APITCH)
#define VS_OFF (2*64*APITCH)
#define PS_OFF (3*64*APITCH)
#define ATT_SMEM (4*64*APITCH*4)

__global__ void __launch_bounds__(256, 2)
attn_kernel(const float* __restrict__ qkv, float* __restrict__ o)
{
    extern __shared__ float sm[];
    const int tid = threadIdx.x;
    const int tx = tid & 15, ty = tid >> 4;
    const int q0 = blockIdx.x * AQ;
    const int h  = blockIdx.y;
    const int b  = blockIdx.z;

    const size_t rowstride = 3 * DMODEL;
    const float* Qg = qkv + (size_t)(b * SEQ) * rowstride + h * HDIM;
    const float* Kg = Qg + DMODEL;
    const float* Vg = Qg + 2 * DMODEL;

#pragma unroll
    for (int it = 0; it < 4; it++) {
        int i = tid + it * 256;
        int q = i >> 4, d = (i & 15) * 4;
        float4 v = *(const float4*)(Qg + (size_t)(q0 + q) * rowstride + d);
        sm[QS_OFF + (d + 0) * APITCH + q] = v.x * 0.125f;
        sm[QS_OFF + (d + 1) * APITCH + q] = v.y * 0.125f;
        sm[QS_OFF + (d + 2) * APITCH + q] = v.z * 0.125f;
        sm[QS_OFF + (d + 3) * APITCH + q] = v.w * 0.125f;
    }

    unsigned long long acc2o[4][2];   // row i, packed d-pairs (4 cols = 2 pairs)
    float mrow[4], lrow[4];
#pragma unroll
    for (int i = 0; i < 4; i++) {
        mrow[i] = -1e30f; lrow[i] = 0.f;
        acc2o[i][0] = 0ull; acc2o[i][1] = 0ull;
    }

    for (int kt = 0; kt < SEQ / AK; kt++) {
        __syncthreads();
#pragma unroll
        for (int it = 0; it < 4; it++) {
            int i = tid + it * 256;
            int k = i >> 4, d = (i & 15) * 4;
            const float* kp = Kg + (size_t)(kt * AK + k) * rowstride + d;
            float4 kv = *(const float4*)(kp);
            sm[KS_OFF + (d + 0) * APITCH + k] = kv.x;
            sm[KS_OFF + (d + 1) * APITCH + k] = kv.y;
            sm[KS_OFF + (d + 2) * APITCH + k] = kv.z;
            sm[KS_OFF + (d + 3) * APITCH + k] = kv.w;
            float4 vv = *(const float4*)(Vg + (size_t)(kt * AK + k) * rowstride + d);
            *(float4*)&sm[VS_OFF + k * APITCH + d] = vv;
        }
        __syncthreads();

        // S = Q^T K  (packed over k-pairs)
        unsigned long long s2[4][2];
#pragma unroll
        for (int i = 0; i < 4; i++) { s2[i][0] = 0ull; s2[i][1] = 0ull; }
#pragma unroll
        for (int d = 0; d < HDIM; d++) {
            float qr[4];
            *(float4*)qr = *(const float4*)&sm[QS_OFF + d * APITCH + ty * 4];
            ulonglong2 kq = *(const ulonglong2*)&sm[KS_OFF + d * APITCH + tx * 4];
#pragma unroll
            for (int i = 0; i < 4; i++) {
                unsigned long long a2;
                PACK_DUP(a2, qr[i]);
                FMA2(s2[i][0], a2, kq.x);
                FMA2(s2[i][1], a2, kq.y);
            }
        }
        float s4[4][4];
#pragma unroll
        for (int i = 0; i < 4; i++) {
            uint32_t l0, h0, l1, h1;
            UNPK(l0, h0, s2[i][0]);
            UNPK(l1, h1, s2[i][1]);
            s4[i][0] = __uint_as_float(l0); s4[i][1] = __uint_as_float(h0);
            s4[i][2] = __uint_as_float(l1); s4[i][3] = __uint_as_float(h1);
        }

        // online softmax per q-row
#pragma unroll
        for (int i = 0; i < 4; i++) {
            float tm = fmaxf(fmaxf(s4[i][0], s4[i][1]), fmaxf(s4[i][2], s4[i][3]));
#pragma unroll
            for (int off = 8; off > 0; off >>= 1)
                tm = fmaxf(tm, __shfl_xor_sync(0xFFFFFFFFu, tm, off, 16));
            float nm = fmaxf(mrow[i], tm);
            float corr = __expf(mrow[i] - nm);
            mrow[i] = nm;
            float rs = 0.f;
#pragma unroll
            for (int j = 0; j < 4; j++) {
                s4[i][j] = __expf(s4[i][j] - nm);
                rs += s4[i][j];
            }
#pragma unroll
            for (int off = 8; off > 0; off >>= 1)
                rs += __shfl_xor_sync(0xFFFFFFFFu, rs, off, 16);
            lrow[i] = lrow[i] * corr + rs;
            unsigned long long c2;
            PACK_DUP(c2, corr);
            MUL2(acc2o[i][0], c2);
            MUL2(acc2o[i][1], c2);
        }

        // stage P transposed
#pragma unroll
        for (int j = 0; j < 4; j++) {
            float4 pv = make_float4(s4[0][j], s4[1][j], s4[2][j], s4[3][j]);
            *(float4*)&sm[PS_OFF + (tx * 4 + j) * APITCH + ty * 4] = pv;
        }
        __syncthreads();

        // O += P V  (packed over d-pairs)
#pragma unroll 4
        for (int k = 0; k < AK; k++) {
            ulonglong2 v2 = *(const ulonglong2*)&sm[VS_OFF + k * APITCH + tx * 4];
            float pq[4];
            pq[0] = sm[PS_OFF + k * APITCH + ty * 4 + 0];
            pq[1] = sm[PS_OFF + k * APITCH + ty * 4 + 1];
            pq[2] = sm[PS_OFF + k * APITCH + ty * 4 + 2];
            pq[3] = sm[PS_OFF + k * APITCH + ty * 4 + 3];
#pragma unroll
            for (int i = 0; i < 4; i++) {
                unsigned long long a2;
                PACK_DUP(a2, pq[i]);
                FMA2(acc2o[i][0], a2, v2.x);
                FMA2(acc2o[i][1], a2, v2.y);
            }
        }
    }

#pragma unroll
    for (int i = 0; i < 4; i++) {
        float inv = 1.0f / lrow[i];
        uint32_t l0, h0, l1, h1;
        UNPK(l0, h0, acc2o[i][0]);
        UNPK(l1, h1, acc2o[i][1]);
        int row = b * SEQ + q0 + ty * 4 + i;
        float4 ov = make_float4(__uint_as_float(l0) * inv, __uint_as_float(h0) * inv,
                                __uint_as_float(l1) * inv, __uint_as_float(h1) * inv);
        *(float4*)(o + (size_t)row * DMODEL + h * HDIM + tx * 4) = ov;
    }
}

// ---------------- lm_head weight pad ----------------
__global__ void pad_kernel(const float* __restrict__ W, float* __restrict__ P) {
    int idx = blockIdx.x * 256 + threadIdx.x;
    if (idx >= DMODEL * VPAD) return;
    int k = idx / VPAD, n = idx - k * VPAD;
    P[idx] = (n < VOCAB) ? W[(size_t)k * VOCAB + n] : 0.f;
}

// ---------------- embedding ----------------
__global__ void embed_tok_kernel(const int* __restrict__ tok,
                                 const float* __restrict__ te,
                                 float* __restrict__ x) {
    int idx = blockIdx.x * blockDim.x + threadIdx.x;
    if (idx >= ROWS * DMODEL) return;
    int row = idx / DMODEL, d = idx % DMODEL;
    x[idx] = te[(size_t)tok[row] * DMODEL + d];
}
__global__ void embed_pos_kernel(const float* __restrict__ pe, float* __restrict__ x) {
    int idx = blockIdx.x * blockDim.x + threadIdx.x;
    if (idx >= ROWS * DMODEL) return;
    int row = idx / DMODEL, d = idx % DMODEL, s = row % SEQ;
    x[idx] += pe[(size_t)s * DMODEL + d];
}

// ---------------- layernorm ----------------
__global__ void ln_kernel(const float* __restrict__ x,
                          const float* __restrict__ g, const float* __restrict__ b,
                          float* __restrict__ y) {
    int row = blockIdx.x;
    const float* xr = x + (size_t)row * DMODEL;
    __shared__ float red[256];
    int tid = threadIdx.x;

    float s = 0.f;
    for (int i = tid; i < DMODEL; i += 256) s += xr[i];
    red[tid] = s; __syncthreads();
    for (int k = 128; k > 0; k >>= 1) { if (tid < k) red[tid] += red[tid + k]; __syncthreads(); }
    float mean = red[0] * (1.0f / DMODEL);
    __syncthreads();

    float v = 0.f;
    for (int i = tid; i < DMODEL; i += 256) { float d = xr[i] - mean; v += d * d; }
    red[tid] = v; __syncthreads();
    for (int k = 128; k > 0; k >>= 1) { if (tid < k) red[tid] += red[tid + k]; __syncthreads(); }
    float rstd = rsqrtf(red[0] * (1.0f / DMODEL) + 1e-5f);

    float* yr = y + (size_t)row * DMODEL;
    for (int i = tid; i < DMODEL; i += 256)
        yr[i] = (xr[i] - mean) * rstd * g[i] + b[i];
}

// ---------------- launch ----------------
extern "C" void kernel_launch(void* const* d_in, const int* in_sizes, int n_in,
                              void* d_out, int out_size) {
    const int*   tokens    = (const int*)  d_in[0];
    const float* tok_embed = (const float*)d_in[1];
    const float* pos_embed = (const float*)d_in[2];
    const float* ln1_g = (const float*)d_in[3];
    const float* ln1_b = (const float*)d_in[4];
    const float* qkv_w = (const float*)d_in[5];
    const float* qkv_b = (const float*)d_in[6];
    const float* proj_w = (const float*)d_in[7];
    const float* proj_b = (const float*)d_in[8];
    const float* ln2_g = (const float*)d_in[9];
    const float* ln2_b = (const float*)d_in[10];
    const float* ff1_w = (const float*)d_in[11];
    const float* ff1_b = (const float*)d_in[12];
    const float* ff2_w = (const float*)d_in[13];
    const float* ff2_b = (const float*)d_in[14];
    const float* lm_w  = (const float*)d_in[15];
    float* out = (float*)d_out;

    float *px, *ph, *pqkv, *po, *pff, *pwlm;
    cudaGetSymbolAddress((void**)&px,   g_x);
    cudaGetSymbolAddress((void**)&ph,   g_h);
    cudaGetSymbolAddress((void**)&pqkv, g_qkv);
    cudaGetSymbolAddress((void**)&po,   g_o);
    cudaGetSymbolAddress((void**)&pff,  g_ff);
    cudaGetSymbolAddress((void**)&pwlm, g_wlm);

    cudaFuncSetAttribute(attn_kernel, cudaFuncAttributeMaxDynamicSharedMemorySize, ATT_SMEM);

    const int EB = (ROWS * DMODEL + 255) / 256;

    for (int l = 0; l < NLAYER; l++) {
        const float* qw = qkv_w + (size_t)l * DMODEL * 3 * DMODEL;
        const float* qb = qkv_b + (size_t)l * 3 * DMODEL;
        const float* pw = proj_w + (size_t)l * DMODEL * DMODEL;
        const float* pb = proj_b + (size_t)l * DMODEL;
        const float* w1 = ff1_w + (size_t)l * DMODEL * FFDIM;
        const float* b1 = ff1_b + (size_t)l * FFDIM;
        const float* w2 = ff2_w + (size_t)l * FFDIM * DMODEL;
        const float* b2 = ff2_b + (size_t)l * DMODEL;

        if (l == 0) {
            embed_tok_kernel<<<EB, 256>>>(tokens, tok_embed, px);
            embed_pos_kernel<<<EB, 256>>>(pos_embed, px);
        }
        ln_kernel<<<ROWS, 256>>>(px, ln1_g + l * DMODEL, ln1_b + l * DMODEL, ph);
        sgemm<0><<<dim3(3 * DMODEL / 128, ROWS / 128), 256>>>(
            ph, qw, qb, nullptr, pqkv, DMODEL, 3 * DMODEL, 3 * DMODEL);
        attn_kernel<<<dim3(SEQ / AQ, NHEAD, BATCH), 256, ATT_SMEM>>>(pqkv, po);
        sgemm<2><<<dim3(DMODEL / 128, ROWS / 128), 256>>>(
            po, pw, pb, px, px, DMODEL, DMODEL, DMODEL);
        ln_kernel<<<ROWS, 256>>>(px, ln2_g + l * DMODEL, ln2_b + l * DMODEL, ph);
        sgemm<1><<<dim3(FFDIM / 128, ROWS / 128), 256>>>(
            ph, w1, b1, nullptr, pff, DMODEL, FFDIM, FFDIM);
        sgemm<2><<<dim3(DMODEL / 128, ROWS / 128), 256>>>(
            pff, w2, b2, px, px, FFDIM, DMODEL, DMODEL);

        if (l == 0) {
            pad_kernel<<<(DMODEL * VPAD + 255) / 256, 256>>>(lm_w, pwlm);
        }
    }

    // logits = x @ lm_head_w   [2048 x 50257], B padded to stride VPAD
    sgemm<3><<<dim3(VPAD / 128, ROWS / 128), 256>>>(
        px, pwlm, nullptr, nullptr, out, DMODEL, VPAD, VOCAB);
}